// round 1
// baseline (speedup 1.0000x reference)
#include <cuda_runtime.h>
#include <cuda_bf16.h>
#include <cstdint>

// Problem constants
#define BB 8
#define SS 2048
#define HH 1024
#define MM (BB * SS)      // 16384
#define KK HH             // 1024
#define NN (3 * HH)       // 3072

// Scratch for the projection output ux = x @ W  [M, 3H]  (201 MB)
__device__ float g_ux[(size_t)MM * NN];

// ---------------------------------------------------------------------------
// Packed f32x2 helpers (sm_100+): full-rate fp32 FMA path
// ---------------------------------------------------------------------------
__device__ __forceinline__ unsigned long long splat2(float a) {
    unsigned long long r;
    asm("mov.b64 %0, {%1, %1};" : "=l"(r) : "f"(a));
    return r;
}
__device__ __forceinline__ void ffma2(unsigned long long& d, unsigned long long a,
                                      unsigned long long b) {
    asm("fma.rn.f32x2 %0, %1, %2, %0;" : "+l"(d) : "l"(a), "l"(b));
}

// ---------------------------------------------------------------------------
// GEMM: C[M,N] = A[M,K] * B[K,N], fp32, 128x128 tile, K-step 8, double-buffered
// 256 threads, 8x8 micro-tile per thread, accumulators packed as f32x2
// ---------------------------------------------------------------------------
#define TM 128
#define TN 128
#define TK 8

__global__ void __launch_bounds__(256) sru_gemm_kernel(const float* __restrict__ A,
                                                       const float* __restrict__ Bw) {
    __shared__ __align__(16) float As[2][TK][TM];  // transposed A tile
    __shared__ __align__(16) float Bs[2][TK][TN];

    const int tid = threadIdx.x;
    const int bm = blockIdx.y * TM;
    const int bn = blockIdx.x * TN;

    const int tx = tid & 15;          // 0..15
    const int ty = tid >> 4;          // 0..15
    const int row0 = ty * 8;
    const int col0 = tx * 8;

    // Global load mapping
    const int arow = tid >> 1;          // 0..127
    const int acol = (tid & 1) * 4;     // 0 or 4
    const int brow = tid >> 5;          // 0..7
    const int bcol = (tid & 31) * 4;    // 0..124

    const float* Aptr = A + (size_t)(bm + arow) * KK + acol;
    const float* Bptr = Bw + (size_t)brow * NN + bn + bcol;

    // Prologue: load k0 = 0 into buffer 0
    float4 av = *(const float4*)Aptr;
    float4 bv = *(const float4*)Bptr;
    As[0][acol + 0][arow] = av.x;
    As[0][acol + 1][arow] = av.y;
    As[0][acol + 2][arow] = av.z;
    As[0][acol + 3][arow] = av.w;
    *(float4*)&Bs[0][brow][bcol] = bv;
    __syncthreads();

    unsigned long long acc[8][4];
#pragma unroll
    for (int i = 0; i < 8; i++)
#pragma unroll
        for (int j = 0; j < 4; j++) acc[i][j] = 0ull;

    int buf = 0;
    for (int k0 = 0; k0 < KK; k0 += TK) {
        const bool has_next = (k0 + TK) < KK;
        float4 av2, bv2;
        if (has_next) {
            av2 = *(const float4*)(Aptr + (k0 + TK));
            bv2 = *(const float4*)(Bptr + (size_t)(k0 + TK) * NN);
        }

#pragma unroll
        for (int kk = 0; kk < TK; kk++) {
            float4 a0 = *(const float4*)&As[buf][kk][row0];
            float4 a1 = *(const float4*)&As[buf][kk][row0 + 4];
            unsigned long long bb[4];
#pragma unroll
            for (int j = 0; j < 4; j++)
                bb[j] = *(const unsigned long long*)&Bs[buf][kk][col0 + 2 * j];
            float ar[8] = {a0.x, a0.y, a0.z, a0.w, a1.x, a1.y, a1.z, a1.w};
#pragma unroll
            for (int i = 0; i < 8; i++) {
                unsigned long long ap = splat2(ar[i]);
#pragma unroll
                for (int j = 0; j < 4; j++) ffma2(acc[i][j], ap, bb[j]);
            }
        }

        if (has_next) {
            const int nb = buf ^ 1;
            As[nb][acol + 0][arow] = av2.x;
            As[nb][acol + 1][arow] = av2.y;
            As[nb][acol + 2][arow] = av2.z;
            As[nb][acol + 3][arow] = av2.w;
            *(float4*)&Bs[nb][brow][bcol] = bv2;
        }
        __syncthreads();
        buf ^= 1;
    }

    // Epilogue: packed 8-byte stores (lane0 of the pair = lower column)
#pragma unroll
    for (int i = 0; i < 8; i++) {
        float* crow = g_ux + (size_t)(bm + row0 + i) * NN + bn + col0;
#pragma unroll
        for (int j = 0; j < 4; j++)
            *(unsigned long long*)(crow + 2 * j) = acc[i][j];
    }
}

// ---------------------------------------------------------------------------
// Scan: 8192 channels (b,h), sequential over t. Register-double-buffered
// prefetch of 8 timesteps; -log2(e) folded into gate pre-activations at load.
// ---------------------------------------------------------------------------
#define CHUNK 8
#define NLOG2E (-1.4426950408889634f)

__device__ __forceinline__ float fast_ex2(float x) {
    float r;
    asm("ex2.approx.ftz.f32 %0, %1;" : "=f"(r) : "f"(x));
    return r;
}
__device__ __forceinline__ float fast_rcp(float x) {
    float r;
    asm("rcp.approx.ftz.f32 %0, %1;" : "=f"(r) : "f"(x));
    return r;
}

__global__ void __launch_bounds__(128) sru_scan_kernel(
    const float* __restrict__ x, const float* __restrict__ vf,
    const float* __restrict__ vr, const float* __restrict__ bf,
    const float* __restrict__ br, float* __restrict__ out) {
    const int idx = blockIdx.x * blockDim.x + threadIdx.x;  // 0..8191
    const int b = idx >> 10;
    const int h = idx & (HH - 1);

    const float vfn = NLOG2E * vf[h];
    const float vrn = NLOG2E * vr[h];
    const float bfh = bf[h];
    const float brh = br[h];

    const float* xp = x + (size_t)b * SS * HH + h;
    const float* up = g_ux + (size_t)b * SS * NN + h;
    float* yp = out + (size_t)b * SS * HH + h;

    float c = 0.0f;

    float axf[CHUNK], axc[CHUNK], axr[CHUNK], ax[CHUNK];
    float bxf[CHUNK], bxc[CHUNK], bxr[CHUNK], bx[CHUNK];

#define LOADC(dxf, dxc, dxr, dx, t0)                                    \
    {                                                                   \
        _Pragma("unroll") for (int u = 0; u < CHUNK; u++) {             \
            const size_t tt = (size_t)((t0) + u);                       \
            dxf[u] = NLOG2E * (up[tt * NN] + bfh);                      \
            dxc[u] = up[tt * NN + HH];                                  \
            dxr[u] = NLOG2E * (up[tt * NN + 2 * HH] + brh);             \
            dx[u]  = xp[tt * HH];                                       \
        }                                                               \
    }

#define STEPC(sxf, sxc, sxr, sx, t0)                                    \
    {                                                                   \
        _Pragma("unroll") for (int u = 0; u < CHUNK; u++) {             \
            const float ct = c;                                         \
            const float ef = fast_ex2(fmaf(vfn, ct, sxf[u]));           \
            const float er = fast_ex2(fmaf(vrn, ct, sxr[u]));           \
            const float ft = fast_rcp(1.0f + ef);                       \
            const float rt = fast_rcp(1.0f + er);                       \
            c = fmaf(ft, ct - sxc[u], sxc[u]);                          \
            yp[(size_t)((t0) + u) * HH] = fmaf(rt, c - sx[u], sx[u]);   \
        }                                                               \
    }

    LOADC(axf, axc, axr, ax, 0);
    for (int t0 = 0; t0 < SS; t0 += 2 * CHUNK) {
        LOADC(bxf, bxc, bxr, bx, t0 + CHUNK);
        STEPC(axf, axc, axr, ax, t0);
        if (t0 + 2 * CHUNK < SS) LOADC(axf, axc, axr, ax, t0 + 2 * CHUNK);
        STEPC(bxf, bxc, bxr, bx, t0 + CHUNK);
    }

    // cfinal appended after y: out[B*S*H + b*H + h]
    out[(size_t)BB * SS * HH + (size_t)b * HH + h] = c;
}

// ---------------------------------------------------------------------------
// Launch
// ---------------------------------------------------------------------------
extern "C" void kernel_launch(void* const* d_in, const int* in_sizes, int n_in,
                              void* d_out, int out_size) {
    const float* x  = (const float*)d_in[0];
    const float* W  = (const float*)d_in[1];
    const float* vf = (const float*)d_in[2];
    const float* vr = (const float*)d_in[3];
    const float* bf = (const float*)d_in[4];
    const float* br = (const float*)d_in[5];
    float* out = (float*)d_out;

    dim3 gemm_grid(NN / TN, MM / TM);  // (24, 128)
    sru_gemm_kernel<<<gemm_grid, 256>>>(x, W);

    sru_scan_kernel<<<(BB * HH) / 128, 128>>>(x, vf, vr, bf, br, out);
}

// round 3
// speedup vs baseline: 2.2244x; 2.2244x over previous
#include <cuda_runtime.h>
#include <cuda_bf16.h>
#include <cstdint>

// ---------------------------------------------------------------------------
// Problem constants
// ---------------------------------------------------------------------------
#define BB 8
#define SS 2048
#define HH 1024
#define MM (BB * SS)      // 16384
#define KK HH             // 1024
#define NN (3 * HH)       // 3072

// Scratch (__device__ globals: allocation-guard-safe)
__device__ float         g_ux[(size_t)MM * NN];     // projection output [M, 3H]
__device__ __nv_bfloat16 g_Ahi[(size_t)MM * KK];    // x hi   [M, K]
__device__ __nv_bfloat16 g_Alo[(size_t)MM * KK];    // x lo   [M, K]
__device__ __nv_bfloat16 g_Bhi[(size_t)NN * KK];    // W^T hi [N, K]
__device__ __nv_bfloat16 g_Blo[(size_t)NN * KK];    // W^T lo [N, K]

// ---------------------------------------------------------------------------
// Helpers
// ---------------------------------------------------------------------------
__device__ __forceinline__ uint32_t s2u(const void* p) {
    uint32_t a;
    asm("{ .reg .u64 t; cvta.to.shared.u64 t, %1; cvt.u32.u64 %0, t; }"
        : "=r"(a) : "l"(p));
    return a;
}

// SW64-style swizzle for 64-byte rows: xor row bits [7:8] into 16B-col bits [4:5]
__device__ __forceinline__ uint32_t sw64(uint32_t o) {
    return o ^ ((o >> 3) & 0x30);
}

#define CP_ASYNC16(smem_u32, gptr)                                      \
    asm volatile("cp.async.cg.shared.global [%0], [%1], 16;"            \
                 :: "r"(smem_u32), "l"(gptr) : "memory")
#define CP_COMMIT() asm volatile("cp.async.commit_group;" ::: "memory")
#define CP_WAIT2()  asm volatile("cp.async.wait_group 2;" ::: "memory")

__device__ __forceinline__ void ldmatrix_x4(uint32_t* r, uint32_t addr) {
    asm volatile("ldmatrix.sync.aligned.m8n8.x4.shared.b16 {%0,%1,%2,%3}, [%4];"
                 : "=r"(r[0]), "=r"(r[1]), "=r"(r[2]), "=r"(r[3])
                 : "r"(addr));
}

__device__ __forceinline__ void mma_bf16(float* c, const uint32_t* a,
                                         uint32_t b0, uint32_t b1) {
    asm volatile(
        "mma.sync.aligned.m16n8k16.row.col.f32.bf16.bf16.f32 "
        "{%0,%1,%2,%3}, {%4,%5,%6,%7}, {%8,%9}, {%0,%1,%2,%3};"
        : "+f"(c[0]), "+f"(c[1]), "+f"(c[2]), "+f"(c[3])
        : "r"(a[0]), "r"(a[1]), "r"(a[2]), "r"(a[3]), "r"(b0), "r"(b1));
}

// ---------------------------------------------------------------------------
// fp32 -> bf16 hi/lo split: A = x (row-major [M,K])
// ---------------------------------------------------------------------------
__global__ void __launch_bounds__(256) cvt_a_kernel(const float* __restrict__ x) {
    size_t i = ((size_t)blockIdx.x * 256 + threadIdx.x) * 4;
    float4 v = *(const float4*)(x + i);
    float f[4] = {v.x, v.y, v.z, v.w};
    __nv_bfloat16 hi[4], lo[4];
#pragma unroll
    for (int j = 0; j < 4; j++) {
        hi[j] = __float2bfloat16(f[j]);
        lo[j] = __float2bfloat16(f[j] - __bfloat162float(hi[j]));
    }
    __nv_bfloat162 h0(hi[0], hi[1]), h1(hi[2], hi[3]);
    __nv_bfloat162 l0(lo[0], lo[1]), l1(lo[2], lo[3]);
    *reinterpret_cast<__nv_bfloat162*>(g_Ahi + i)     = h0;
    *reinterpret_cast<__nv_bfloat162*>(g_Ahi + i + 2) = h1;
    *reinterpret_cast<__nv_bfloat162*>(g_Alo + i)     = l0;
    *reinterpret_cast<__nv_bfloat162*>(g_Alo + i + 2) = l1;
}

// ---------------------------------------------------------------------------
// W [K,N] fp32 -> transposed bf16 hi/lo [N,K]
// ---------------------------------------------------------------------------
__global__ void __launch_bounds__(256) cvt_w_kernel(const float* __restrict__ W) {
    __shared__ float s[32][33];
    const int n0 = blockIdx.x * 32, k0 = blockIdx.y * 32;
    const int tx = threadIdx.x & 31, ty = threadIdx.x >> 5;  // ty 0..7
#pragma unroll
    for (int i = 0; i < 4; i++)
        s[ty + 8 * i][tx] = W[(size_t)(k0 + ty + 8 * i) * NN + n0 + tx];
    __syncthreads();
#pragma unroll
    for (int i = 0; i < 4; i++) {
        const int n = n0 + ty + 8 * i;
        const int k = k0 + tx;
        const float f = s[tx][ty + 8 * i];
        __nv_bfloat16 hi = __float2bfloat16(f);
        __nv_bfloat16 lo = __float2bfloat16(f - __bfloat162float(hi));
        g_Bhi[(size_t)n * KK + k] = hi;
        g_Blo[(size_t)n * KK + k] = lo;
    }
}

// ---------------------------------------------------------------------------
// GEMM: C[M,N] = sum over K' = 3K of split products, via mma.sync bf16
// CTA tile 128x128, BK=32, 3-stage cp.async pipeline, 8 warps (64x32 each)
// ---------------------------------------------------------------------------
#define BK 32
#define STAGE_B 16384                       // A 8KB + B 8KB per stage
#define NCHUNK (3 * KK / BK)                // 96

__device__ __forceinline__ void load_chunk(int c, int tid, int bm, int bn,
                                           uint32_t sb) {
    const int third = c >> 5;               // 0: hi*hi  1: hi*lo  2: lo*hi
    const int kk0 = (c & 31) * BK;
    const __nv_bfloat16* Ap = (third == 2) ? g_Alo : g_Ahi;
    const __nv_bfloat16* Bp = (third == 1) ? g_Blo : g_Bhi;
    const uint32_t dst = sb + (uint32_t)(c % 3) * STAGE_B;
#pragma unroll
    for (int i = 0; i < 2; i++) {
        const int idx = tid + i * 256;      // 0..511
        const int row = idx >> 2;           // 0..127
        const int c16 = idx & 3;            // 16B column
        const uint32_t so = sw64((uint32_t)(row * 64 + c16 * 16));
        CP_ASYNC16(dst + so,        Ap + (size_t)(bm + row) * KK + kk0 + c16 * 8);
        CP_ASYNC16(dst + 8192 + so, Bp + (size_t)(bn + row) * KK + kk0 + c16 * 8);
    }
}

__global__ void __launch_bounds__(256) sru_mma_gemm() {
    __shared__ __align__(128) char smr[3 * STAGE_B];   // 48 KB
    const uint32_t sb = s2u(smr);
    const int tid = threadIdx.x;
    const int wid = tid >> 5;
    const int l = tid & 31;
    const int wm = wid >> 2;                // 0..1 -> M offset *64
    const int wn = wid & 3;                 // 0..3 -> N offset *32
    const int bm = blockIdx.y * 128;
    const int bn = blockIdx.x * 128;

    float acc[4][4][4];
#pragma unroll
    for (int i = 0; i < 4; i++)
#pragma unroll
        for (int j = 0; j < 4; j++)
#pragma unroll
            for (int k = 0; k < 4; k++) acc[i][j][k] = 0.0f;

    // Precompute per-lane swizzled ldmatrix offsets
    uint32_t aoff[4][2], boff[2][2];
#pragma unroll
    for (int mt = 0; mt < 4; mt++)
#pragma unroll
        for (int k16 = 0; k16 < 2; k16++) {
            const uint32_t o = (uint32_t)((wm * 64 + mt * 16 + (l & 15)) * 64 +
                                          k16 * 32 + (l >> 4) * 16);
            aoff[mt][k16] = sw64(o);
        }
#pragma unroll
    for (int nb = 0; nb < 2; nb++)
#pragma unroll
        for (int k16 = 0; k16 < 2; k16++) {
            const int n = wn * 32 + nb * 16 + ((l >> 4) << 3) + (l & 7);
            const uint32_t o = (uint32_t)(n * 64 + k16 * 32 + ((l >> 3) & 1) * 16);
            boff[nb][k16] = 8192u + sw64(o);
        }

    // Prologue: stages 0..2
#pragma unroll
    for (int p = 0; p < 3; p++) {
        load_chunk(p, tid, bm, bn, sb);
        CP_COMMIT();
    }

    for (int c = 0; c < NCHUNK; c++) {
        CP_WAIT2();                         // chunk c resident
        __syncthreads();

        const uint32_t base = sb + (uint32_t)(c % 3) * STAGE_B;
#pragma unroll
        for (int k16 = 0; k16 < 2; k16++) {
            uint32_t a[4][4], b[2][4];
#pragma unroll
            for (int mt = 0; mt < 4; mt++) ldmatrix_x4(a[mt], base + aoff[mt][k16]);
#pragma unroll
            for (int nb = 0; nb < 2; nb++) ldmatrix_x4(b[nb], base + boff[nb][k16]);
#pragma unroll
            for (int mt = 0; mt < 4; mt++)
#pragma unroll
                for (int nt = 0; nt < 4; nt++)
                    mma_bf16(acc[mt][nt], a[mt], b[nt >> 1][(nt & 1) * 2],
                             b[nt >> 1][(nt & 1) * 2 + 1]);
        }
        __syncthreads();

        if (c + 3 < NCHUNK) load_chunk(c + 3, tid, bm, bn, sb);
        CP_COMMIT();
    }

    // Epilogue: fragment-direct float2 stores (4 lanes cover 32B contiguous)
    const int g = l >> 2;
    const int t4 = l & 3;
#pragma unroll
    for (int mt = 0; mt < 4; mt++) {
        const size_t r0 = (size_t)(bm + wm * 64 + mt * 16 + g);
#pragma unroll
        for (int nt = 0; nt < 4; nt++) {
            const int col = bn + wn * 32 + nt * 8 + t4 * 2;
            float2 v0 = make_float2(acc[mt][nt][0], acc[mt][nt][1]);
            float2 v1 = make_float2(acc[mt][nt][2], acc[mt][nt][3]);
            *reinterpret_cast<float2*>(g_ux + r0 * NN + col)       = v0;
            *reinterpret_cast<float2*>(g_ux + (r0 + 8) * NN + col) = v1;
        }
    }
}

// ---------------------------------------------------------------------------
// Scan: 8192 channels (b,h), sequential over t
// ---------------------------------------------------------------------------
#define CHUNK 8
#define NLOG2E (-1.4426950408889634f)

__device__ __forceinline__ float fast_ex2(float x) {
    float r;
    asm("ex2.approx.ftz.f32 %0, %1;" : "=f"(r) : "f"(x));
    return r;
}
__device__ __forceinline__ float fast_rcp(float x) {
    float r;
    asm("rcp.approx.ftz.f32 %0, %1;" : "=f"(r) : "f"(x));
    return r;
}

__global__ void __launch_bounds__(32) sru_scan_kernel(
    const float* __restrict__ x, const float* __restrict__ vf,
    const float* __restrict__ vr, const float* __restrict__ bf,
    const float* __restrict__ br, float* __restrict__ out) {
    const int idx = blockIdx.x * 32 + threadIdx.x;  // 0..8191
    const int b = idx >> 10;
    const int h = idx & (HH - 1);

    const float vfn = NLOG2E * vf[h];
    const float vrn = NLOG2E * vr[h];
    const float bfh = bf[h];
    const float brh = br[h];

    const float* xp = x + (size_t)b * SS * HH + h;
    const float* up = g_ux + (size_t)b * SS * NN + h;
    float* yp = out + (size_t)b * SS * HH + h;

    float c = 0.0f;

    float axf[CHUNK], axc[CHUNK], axr[CHUNK], ax[CHUNK];
    float bxf[CHUNK], bxc[CHUNK], bxr[CHUNK], bx[CHUNK];

#define LOADC(dxf, dxc, dxr, dx, t0)                                    \
    {                                                                   \
        _Pragma("unroll") for (int u = 0; u < CHUNK; u++) {             \
            const size_t tt = (size_t)((t0) + u);                       \
            dxf[u] = NLOG2E * (up[tt * NN] + bfh);                      \
            dxc[u] = up[tt * NN + HH];                                  \
            dxr[u] = NLOG2E * (up[tt * NN + 2 * HH] + brh);             \
            dx[u]  = xp[tt * HH];                                       \
        }                                                               \
    }

#define STEPC(sxf, sxc, sxr, sx, t0)                                    \
    {                                                                   \
        _Pragma("unroll") for (int u = 0; u < CHUNK; u++) {             \
            const float ct = c;                                         \
            const float ef = fast_ex2(fmaf(vfn, ct, sxf[u]));           \
            const float er = fast_ex2(fmaf(vrn, ct, sxr[u]));           \
            const float ft = fast_rcp(1.0f + ef);                       \
            const float rt = fast_rcp(1.0f + er);                       \
            c = fmaf(ft, ct - sxc[u], sxc[u]);                          \
            yp[(size_t)((t0) + u) * HH] = fmaf(rt, c - sx[u], sx[u]);   \
        }                                                               \
    }

    LOADC(axf, axc, axr, ax, 0);
    for (int t0 = 0; t0 < SS; t0 += 2 * CHUNK) {
        LOADC(bxf, bxc, bxr, bx, t0 + CHUNK);
        STEPC(axf, axc, axr, ax, t0);
        if (t0 + 2 * CHUNK < SS) LOADC(axf, axc, axr, ax, t0 + 2 * CHUNK);
        STEPC(bxf, bxc, bxr, bx, t0 + CHUNK);
    }

    out[(size_t)BB * SS * HH + (size_t)b * HH + h] = c;
}

// ---------------------------------------------------------------------------
// Launch
// ---------------------------------------------------------------------------
extern "C" void kernel_launch(void* const* d_in, const int* in_sizes, int n_in,
                              void* d_out, int out_size) {
    const float* x  = (const float*)d_in[0];
    const float* W  = (const float*)d_in[1];
    const float* vf = (const float*)d_in[2];
    const float* vr = (const float*)d_in[3];
    const float* bf = (const float*)d_in[4];
    const float* br = (const float*)d_in[5];
    float* out = (float*)d_out;

    cvt_a_kernel<<<(MM * KK) / 1024, 256>>>(x);
    cvt_w_kernel<<<dim3(NN / 32, KK / 32), 256>>>(W);

    dim3 gg(NN / 128, MM / 128);  // (24, 128)
    sru_mma_gemm<<<gg, 256>>>();

    sru_scan_kernel<<<(BB * HH) / 32, 32>>>(x, vf, vr, bf, br, out);
}

// round 4
// speedup vs baseline: 2.7434x; 1.2333x over previous
#include <cuda_runtime.h>
#include <cuda_bf16.h>
#include <cstdint>

// ---------------------------------------------------------------------------
// Problem constants
// ---------------------------------------------------------------------------
#define BB 8
#define SS 2048
#define HH 1024
#define MM (BB * SS)      // 16384
#define KK HH             // 1024
#define NN (3 * HH)       // 3072

// Scratch (__device__ globals: allocation-guard-safe)
__device__ float         g_ux[(size_t)MM * NN];     // projection output [M, 3H]
__device__ __nv_bfloat16 g_Ahi[(size_t)MM * KK];    // x hi   [M, K]
__device__ __nv_bfloat16 g_Alo[(size_t)MM * KK];    // x lo   [M, K]
__device__ __nv_bfloat16 g_Bhi[(size_t)NN * KK];    // W^T hi [N, K]
__device__ __nv_bfloat16 g_Blo[(size_t)NN * KK];    // W^T lo [N, K]

// ---------------------------------------------------------------------------
// Helpers
// ---------------------------------------------------------------------------
__device__ __forceinline__ uint32_t s2u(const void* p) {
    uint32_t a;
    asm("{ .reg .u64 t; cvta.to.shared.u64 t, %1; cvt.u32.u64 %0, t; }"
        : "=r"(a) : "l"(p));
    return a;
}

// SW64-style swizzle for 64-byte rows
__device__ __forceinline__ uint32_t sw64(uint32_t o) {
    return o ^ ((o >> 3) & 0x30);
}

#define CP_ASYNC16(smem_u32, gptr)                                      \
    asm volatile("cp.async.cg.shared.global [%0], [%1], 16;"            \
                 :: "r"(smem_u32), "l"(gptr) : "memory")
#define CP_COMMIT() asm volatile("cp.async.commit_group;" ::: "memory")
#define CP_WAIT2()  asm volatile("cp.async.wait_group 2;" ::: "memory")

__device__ __forceinline__ void ldmatrix_x4(uint32_t* r, uint32_t addr) {
    asm volatile("ldmatrix.sync.aligned.m8n8.x4.shared.b16 {%0,%1,%2,%3}, [%4];"
                 : "=r"(r[0]), "=r"(r[1]), "=r"(r[2]), "=r"(r[3])
                 : "r"(addr));
}

__device__ __forceinline__ void mma_bf16(float* c, const uint32_t* a,
                                         uint32_t b0, uint32_t b1) {
    asm volatile(
        "mma.sync.aligned.m16n8k16.row.col.f32.bf16.bf16.f32 "
        "{%0,%1,%2,%3}, {%4,%5,%6,%7}, {%8,%9}, {%0,%1,%2,%3};"
        : "+f"(c[0]), "+f"(c[1]), "+f"(c[2]), "+f"(c[3])
        : "r"(a[0]), "r"(a[1]), "r"(a[2]), "r"(a[3]), "r"(b0), "r"(b1));
}

// ---------------------------------------------------------------------------
// fp32 -> bf16 hi/lo split: A = x (row-major [M,K])
// ---------------------------------------------------------------------------
__global__ void __launch_bounds__(256) cvt_a_kernel(const float* __restrict__ x) {
    size_t i = ((size_t)blockIdx.x * 256 + threadIdx.x) * 4;
    float4 v = *(const float4*)(x + i);
    float f[4] = {v.x, v.y, v.z, v.w};
    __nv_bfloat16 hi[4], lo[4];
#pragma unroll
    for (int j = 0; j < 4; j++) {
        hi[j] = __float2bfloat16(f[j]);
        lo[j] = __float2bfloat16(f[j] - __bfloat162float(hi[j]));
    }
    __nv_bfloat162 h0(hi[0], hi[1]), h1(hi[2], hi[3]);
    __nv_bfloat162 l0(lo[0], lo[1]), l1(lo[2], lo[3]);
    *reinterpret_cast<__nv_bfloat162*>(g_Ahi + i)     = h0;
    *reinterpret_cast<__nv_bfloat162*>(g_Ahi + i + 2) = h1;
    *reinterpret_cast<__nv_bfloat162*>(g_Alo + i)     = l0;
    *reinterpret_cast<__nv_bfloat162*>(g_Alo + i + 2) = l1;
}

// ---------------------------------------------------------------------------
// W [K,N] fp32 -> transposed bf16 hi/lo [N,K]
// ---------------------------------------------------------------------------
__global__ void __launch_bounds__(256) cvt_w_kernel(const float* __restrict__ W) {
    __shared__ float s[32][33];
    const int n0 = blockIdx.x * 32, k0 = blockIdx.y * 32;
    const int tx = threadIdx.x & 31, ty = threadIdx.x >> 5;  // ty 0..7
#pragma unroll
    for (int i = 0; i < 4; i++)
        s[ty + 8 * i][tx] = W[(size_t)(k0 + ty + 8 * i) * NN + n0 + tx];
    __syncthreads();
#pragma unroll
    for (int i = 0; i < 4; i++) {
        const int n = n0 + ty + 8 * i;
        const int k = k0 + tx;
        const float f = s[tx][ty + 8 * i];
        __nv_bfloat16 hi = __float2bfloat16(f);
        __nv_bfloat16 lo = __float2bfloat16(f - __bfloat162float(hi));
        g_Bhi[(size_t)n * KK + k] = hi;
        g_Blo[(size_t)n * KK + k] = lo;
    }
}

// ---------------------------------------------------------------------------
// GEMM: C[M,N] = sum over K' = 3K of split products, via mma.sync bf16
// CTA tile 128x128, BK=32, 4-stage cp.async pipeline, single sync/iter
// ---------------------------------------------------------------------------
#define BK 32
#define STAGE_B 16384                       // A 8KB + B 8KB per stage
#define NSTAGE 4
#define GEMM_SMEM (NSTAGE * STAGE_B)        // 64 KB (dynamic)
#define NCHUNK (3 * KK / BK)                // 96

__device__ __forceinline__ void load_chunk(int c, int tid, int bm, int bn,
                                           uint32_t sb) {
    const int third = c >> 5;               // 0: hi*hi  1: hi*lo  2: lo*hi
    const int kk0 = (c & 31) * BK;
    const __nv_bfloat16* Ap = (third == 2) ? g_Alo : g_Ahi;
    const __nv_bfloat16* Bp = (third == 1) ? g_Blo : g_Bhi;
    const uint32_t dst = sb + (uint32_t)(c & (NSTAGE - 1)) * STAGE_B;
#pragma unroll
    for (int i = 0; i < 2; i++) {
        const int idx = tid + i * 256;      // 0..511
        const int row = idx >> 2;           // 0..127
        const int c16 = idx & 3;            // 16B column
        const uint32_t so = sw64((uint32_t)(row * 64 + c16 * 16));
        CP_ASYNC16(dst + so,        Ap + (size_t)(bm + row) * KK + kk0 + c16 * 8);
        CP_ASYNC16(dst + 8192 + so, Bp + (size_t)(bn + row) * KK + kk0 + c16 * 8);
    }
}

__global__ void __launch_bounds__(256) sru_mma_gemm() {
    extern __shared__ __align__(128) char smr[];
    const uint32_t sb = s2u(smr);
    const int tid = threadIdx.x;
    const int wid = tid >> 5;
    const int l = tid & 31;
    const int wm = wid >> 2;                // 0..1 -> M offset *64
    const int wn = wid & 3;                 // 0..3 -> N offset *32
    const int bm = blockIdx.y * 128;
    const int bn = blockIdx.x * 128;

    float acc[4][4][4];
#pragma unroll
    for (int i = 0; i < 4; i++)
#pragma unroll
        for (int j = 0; j < 4; j++)
#pragma unroll
            for (int k = 0; k < 4; k++) acc[i][j][k] = 0.0f;

    // Precompute per-lane swizzled ldmatrix offsets
    uint32_t aoff[4][2], boff[2][2];
#pragma unroll
    for (int mt = 0; mt < 4; mt++)
#pragma unroll
        for (int k16 = 0; k16 < 2; k16++) {
            const uint32_t o = (uint32_t)((wm * 64 + mt * 16 + (l & 15)) * 64 +
                                          k16 * 32 + (l >> 4) * 16);
            aoff[mt][k16] = sw64(o);
        }
#pragma unroll
    for (int nb = 0; nb < 2; nb++)
#pragma unroll
        for (int k16 = 0; k16 < 2; k16++) {
            const int n = wn * 32 + nb * 16 + ((l >> 4) << 3) + (l & 7);
            const uint32_t o = (uint32_t)(n * 64 + k16 * 32 + ((l >> 3) & 1) * 16);
            boff[nb][k16] = 8192u + sw64(o);
        }

    // Prologue: chunks 0..2 into stages 0..2
#pragma unroll
    for (int p = 0; p < 3; p++) {
        load_chunk(p, tid, bm, bn, sb);
        CP_COMMIT();
    }

    for (int c = 0; c < NCHUNK; c++) {
        CP_WAIT2();                         // chunk c resident
        __syncthreads();                    // also fences reads of buf (c+3)%4 from iter c-1

        // Issue next load BEFORE compute: buffer (c+3)%4 != c%4, safe post-sync
        if (c + 3 < NCHUNK) load_chunk(c + 3, tid, bm, bn, sb);
        CP_COMMIT();

        const uint32_t base = sb + (uint32_t)(c & (NSTAGE - 1)) * STAGE_B;
#pragma unroll
        for (int k16 = 0; k16 < 2; k16++) {
            uint32_t a[4][4], b[2][4];
#pragma unroll
            for (int mt = 0; mt < 4; mt++) ldmatrix_x4(a[mt], base + aoff[mt][k16]);
#pragma unroll
            for (int nb = 0; nb < 2; nb++) ldmatrix_x4(b[nb], base + boff[nb][k16]);
#pragma unroll
            for (int mt = 0; mt < 4; mt++)
#pragma unroll
                for (int nt = 0; nt < 4; nt++)
                    mma_bf16(acc[mt][nt], a[mt], b[nt >> 1][(nt & 1) * 2],
                             b[nt >> 1][(nt & 1) * 2 + 1]);
        }
    }

    // Epilogue: fragment-direct float2 stores (4 lanes cover 32B contiguous)
    const int g = l >> 2;
    const int t4 = l & 3;
#pragma unroll
    for (int mt = 0; mt < 4; mt++) {
        const size_t r0 = (size_t)(bm + wm * 64 + mt * 16 + g);
#pragma unroll
        for (int nt = 0; nt < 4; nt++) {
            const int col = bn + wn * 32 + nt * 8 + t4 * 2;
            float2 v0 = make_float2(acc[mt][nt][0], acc[mt][nt][1]);
            float2 v1 = make_float2(acc[mt][nt][2], acc[mt][nt][3]);
            *reinterpret_cast<float2*>(g_ux + r0 * NN + col)       = v0;
            *reinterpret_cast<float2*>(g_ux + (r0 + 8) * NN + col) = v1;
        }
    }
}

// ---------------------------------------------------------------------------
// Scan: 8192 channels, one warp per 32 channels, cp.async smem pipeline
// 4 buffers x 16 timesteps x 4 streams x 32 channels = 32 KB
// ---------------------------------------------------------------------------
#define TSTG 16
#define SNSTG 4
#define NLOG2E (-1.4426950408889634f)

__device__ __forceinline__ float fast_ex2(float x) {
    float r;
    asm("ex2.approx.ftz.f32 %0, %1;" : "=f"(r) : "f"(x));
    return r;
}
__device__ __forceinline__ float fast_rcp(float x) {
    float r;
    asm("rcp.approx.ftz.f32 %0, %1;" : "=f"(r) : "f"(x));
    return r;
}

__global__ void __launch_bounds__(32) sru_scan_kernel(
    const float* __restrict__ x, const float* __restrict__ vf,
    const float* __restrict__ vr, const float* __restrict__ bf,
    const float* __restrict__ br, float* __restrict__ out) {
    __shared__ __align__(16) float s[SNSTG][TSTG][4][32];

    const int l = threadIdx.x;
    const int b = blockIdx.x >> 5;              // 32 blocks per batch
    const int h0 = (blockIdx.x & 31) * 32;
    const int h = h0 + l;

    // cp.async lane mapping: stream = l>>3 (0..3), 16B chunk q = l&7
    const int strm = l >> 3;
    const int q = l & 7;

    // Per-lane global source base (element offset for t=0)
    const float* gsrc;
    size_t gstride;
    if (strm < 3) {
        gsrc = g_ux + (size_t)b * SS * NN + (size_t)strm * HH + h0 + q * 4;
        gstride = NN;
    } else {
        gsrc = x + (size_t)b * SS * HH + h0 + q * 4;
        gstride = HH;
    }
    const uint32_t sbase = s2u(&s[0][0][0][0]);

    const float vfn = NLOG2E * vf[h];
    const float vrn = NLOG2E * vr[h];
    const float bfh = bf[h];
    const float brh = br[h];
    float* yp = out + (size_t)b * SS * HH + h;

#define LOAD_STAGE(st, t0)                                                   \
    {                                                                        \
        const uint32_t d0 = sbase + (uint32_t)((st) & (SNSTG - 1)) * 8192 +  \
                            (uint32_t)(strm * 128 + q * 16);                 \
        _Pragma("unroll") for (int t = 0; t < TSTG; t++) {                   \
            CP_ASYNC16(d0 + (uint32_t)t * 512, gsrc + (size_t)((t0) + t) * gstride); \
        }                                                                    \
        CP_COMMIT();                                                         \
    }

    // Prologue: stages 0..2
    LOAD_STAGE(0, 0);
    LOAD_STAGE(1, TSTG);
    LOAD_STAGE(2, 2 * TSTG);

    float c = 0.0f;
    const int NST = SS / TSTG;  // 128
    for (int st = 0; st < NST; st++) {
        CP_WAIT2();
        __syncwarp();

        if (st + 3 < NST) {
            LOAD_STAGE(st + 3, (st + 3) * TSTG);
        } else {
            CP_COMMIT();  // keep group counting aligned
        }

        const float(*sp)[4][32] = s[st & (SNSTG - 1)];
        const int tb = st * TSTG;
#pragma unroll
        for (int t = 0; t < TSTG; t++) {
            const float xf = sp[t][0][l];
            const float xc = sp[t][1][l];
            const float xr = sp[t][2][l];
            const float xv = sp[t][3][l];
            const float ct = c;
            const float ef = fast_ex2(fmaf(vfn, ct, NLOG2E * (xf + bfh)));
            const float er = fast_ex2(fmaf(vrn, ct, NLOG2E * (xr + brh)));
            const float ft = fast_rcp(1.0f + ef);
            const float rt = fast_rcp(1.0f + er);
            c = fmaf(ft, ct - xc, xc);
            yp[(size_t)(tb + t) * HH] = fmaf(rt, c - xv, xv);
        }
        __syncwarp();
    }

    // cfinal appended after y
    out[(size_t)BB * SS * HH + (size_t)b * HH + h] = c;
}

// ---------------------------------------------------------------------------
// Launch
// ---------------------------------------------------------------------------
extern "C" void kernel_launch(void* const* d_in, const int* in_sizes, int n_in,
                              void* d_out, int out_size) {
    const float* x  = (const float*)d_in[0];
    const float* W  = (const float*)d_in[1];
    const float* vf = (const float*)d_in[2];
    const float* vr = (const float*)d_in[3];
    const float* bf = (const float*)d_in[4];
    const float* br = (const float*)d_in[5];
    float* out = (float*)d_out;

    cvt_a_kernel<<<(MM * KK) / 1024, 256>>>(x);
    cvt_w_kernel<<<dim3(NN / 32, KK / 32), 256>>>(W);

    cudaFuncSetAttribute(sru_mma_gemm,
                         cudaFuncAttributeMaxDynamicSharedMemorySize, GEMM_SMEM);
    dim3 gg(NN / 128, MM / 128);  // (24, 128)
    sru_mma_gemm<<<gg, 256, GEMM_SMEM>>>();

    sru_scan_kernel<<<(BB * HH) / 32, 32>>>(x, vf, vr, bf, br, out);
}

// round 5
// speedup vs baseline: 3.0871x; 1.1253x over previous
#include <cuda_runtime.h>
#include <cuda_bf16.h>
#include <cstdint>

// ---------------------------------------------------------------------------
// Problem constants
// ---------------------------------------------------------------------------
#define BB 8
#define SS 2048
#define HH 1024
#define MM (BB * SS)      // 16384
#define KK HH             // 1024
#define NN (3 * HH)       // 3072

// Scratch (__device__ globals: allocation-guard-safe)
__device__ float         g_ux[(size_t)MM * NN];     // projection output [M, 3H]
__device__ __nv_bfloat16 g_Ahi[(size_t)MM * KK];    // x hi   [M, K]
__device__ __nv_bfloat16 g_Alo[(size_t)MM * KK];    // x lo   [M, K]
__device__ __nv_bfloat16 g_Bhi[(size_t)NN * KK];    // W^T hi [N, K]
__device__ __nv_bfloat16 g_Blo[(size_t)NN * KK];    // W^T lo [N, K]

// ---------------------------------------------------------------------------
// Helpers
// ---------------------------------------------------------------------------
__device__ __forceinline__ uint32_t s2u(const void* p) {
    uint32_t a;
    asm("{ .reg .u64 t; cvta.to.shared.u64 t, %1; cvt.u32.u64 %0, t; }"
        : "=r"(a) : "l"(p));
    return a;
}

// SW128 swizzle for 128-byte rows
__device__ __forceinline__ uint32_t sw128(uint32_t o) {
    return o ^ ((o >> 3) & 0x70);
}

#define CP_ASYNC16(smem_u32, gptr)                                      \
    asm volatile("cp.async.cg.shared.global [%0], [%1], 16;"            \
                 :: "r"(smem_u32), "l"(gptr) : "memory")
#define CP_COMMIT() asm volatile("cp.async.commit_group;" ::: "memory")
#define CP_WAIT1()  asm volatile("cp.async.wait_group 1;" ::: "memory")
#define CP_WAIT2()  asm volatile("cp.async.wait_group 2;" ::: "memory")

__device__ __forceinline__ void ldmatrix_x4(uint32_t* r, uint32_t addr) {
    asm volatile("ldmatrix.sync.aligned.m8n8.x4.shared.b16 {%0,%1,%2,%3}, [%4];"
                 : "=r"(r[0]), "=r"(r[1]), "=r"(r[2]), "=r"(r[3])
                 : "r"(addr));
}

__device__ __forceinline__ void mma_bf16(float* c, const uint32_t* a,
                                         uint32_t b0, uint32_t b1) {
    asm volatile(
        "mma.sync.aligned.m16n8k16.row.col.f32.bf16.bf16.f32 "
        "{%0,%1,%2,%3}, {%4,%5,%6,%7}, {%8,%9}, {%0,%1,%2,%3};"
        : "+f"(c[0]), "+f"(c[1]), "+f"(c[2]), "+f"(c[3])
        : "r"(a[0]), "r"(a[1]), "r"(a[2]), "r"(a[3]), "r"(b0), "r"(b1));
}

// ---------------------------------------------------------------------------
// fp32 -> bf16 hi/lo split: A = x (row-major [M,K])
// ---------------------------------------------------------------------------
__global__ void __launch_bounds__(256) cvt_a_kernel(const float* __restrict__ x) {
    size_t i = ((size_t)blockIdx.x * 256 + threadIdx.x) * 4;
    float4 v = *(const float4*)(x + i);
    float f[4] = {v.x, v.y, v.z, v.w};
    __nv_bfloat16 hi[4], lo[4];
#pragma unroll
    for (int j = 0; j < 4; j++) {
        hi[j] = __float2bfloat16(f[j]);
        lo[j] = __float2bfloat16(f[j] - __bfloat162float(hi[j]));
    }
    __nv_bfloat162 h0(hi[0], hi[1]), h1(hi[2], hi[3]);
    __nv_bfloat162 l0(lo[0], lo[1]), l1(lo[2], lo[3]);
    *reinterpret_cast<__nv_bfloat162*>(g_Ahi + i)     = h0;
    *reinterpret_cast<__nv_bfloat162*>(g_Ahi + i + 2) = h1;
    *reinterpret_cast<__nv_bfloat162*>(g_Alo + i)     = l0;
    *reinterpret_cast<__nv_bfloat162*>(g_Alo + i + 2) = l1;
}

// ---------------------------------------------------------------------------
// W [K,N] fp32 -> transposed bf16 hi/lo [N,K]
// ---------------------------------------------------------------------------
__global__ void __launch_bounds__(256) cvt_w_kernel(const float* __restrict__ W) {
    __shared__ float s[32][33];
    const int n0 = blockIdx.x * 32, k0 = blockIdx.y * 32;
    const int tx = threadIdx.x & 31, ty = threadIdx.x >> 5;  // ty 0..7
#pragma unroll
    for (int i = 0; i < 4; i++)
        s[ty + 8 * i][tx] = W[(size_t)(k0 + ty + 8 * i) * NN + n0 + tx];
    __syncthreads();
#pragma unroll
    for (int i = 0; i < 4; i++) {
        const int n = n0 + ty + 8 * i;
        const int k = k0 + tx;
        const float f = s[tx][ty + 8 * i];
        __nv_bfloat16 hi = __float2bfloat16(f);
        __nv_bfloat16 lo = __float2bfloat16(f - __bfloat162float(hi));
        g_Bhi[(size_t)n * KK + k] = hi;
        g_Blo[(size_t)n * KK + k] = lo;
    }
}

// ---------------------------------------------------------------------------
// GEMM: C[M,N] = sum over K' = 3K of split products, via mma.sync bf16
// CTA tile 128x128, BK=64, 3-stage cp.async pipeline, 8 warps (64x32 each)
// ---------------------------------------------------------------------------
#define BK 64
#define STAGE_B 32768                       // A 16KB + B 16KB per stage
#define NSTAGE 3
#define GEMM_SMEM (NSTAGE * STAGE_B)        // 96 KB (dynamic)
#define NCHUNK (3 * KK / BK)                // 48

__device__ __forceinline__ void load_chunk(int c, int tid, int bm, int bn,
                                           uint32_t sb) {
    const int third = c >> 4;               // 0: hi*hi  1: hi*lo  2: lo*hi
    const int kk0 = (c & 15) * BK;
    const __nv_bfloat16* Ap = (third == 2) ? g_Alo : g_Ahi;
    const __nv_bfloat16* Bp = (third == 1) ? g_Blo : g_Bhi;
    const uint32_t dst = sb + (uint32_t)(c % NSTAGE) * STAGE_B;
#pragma unroll
    for (int i = 0; i < 4; i++) {
        const int idx = tid + i * 256;      // 0..1023
        const int row = idx >> 3;           // 0..127
        const int c16 = idx & 7;            // 16B column (128B row)
        const uint32_t so = sw128((uint32_t)(row * 128 + c16 * 16));
        CP_ASYNC16(dst + so,         Ap + (size_t)(bm + row) * KK + kk0 + c16 * 8);
        CP_ASYNC16(dst + 16384 + so, Bp + (size_t)(bn + row) * KK + kk0 + c16 * 8);
    }
}

__global__ void __launch_bounds__(256, 2) sru_mma_gemm() {
    extern __shared__ __align__(128) char smr[];
    const uint32_t sb = s2u(smr);
    const int tid = threadIdx.x;
    const int wid = tid >> 5;
    const int l = tid & 31;
    const int wm = wid >> 2;                // 0..1 -> M offset *64
    const int wn = wid & 3;                 // 0..3 -> N offset *32
    const int bm = blockIdx.y * 128;
    const int bn = blockIdx.x * 128;

    float acc[4][4][4];
#pragma unroll
    for (int i = 0; i < 4; i++)
#pragma unroll
        for (int j = 0; j < 4; j++)
#pragma unroll
            for (int k = 0; k < 4; k++) acc[i][j][k] = 0.0f;

    // Precomputed base (k16=0) swizzled ldmatrix offsets.
    // k16 advance = +32B pre-swizzle; base col bits don't reach swizzle source
    // bits, so sw128(o | k16*32) == sw128(o) ^ (k16*32): XOR at use site.
    uint32_t aoff[4], boff[2];
#pragma unroll
    for (int mt = 0; mt < 4; mt++) {
        const uint32_t o = (uint32_t)((wm * 64 + mt * 16 + (l & 15)) * 128 +
                                      (l >> 4) * 16);
        aoff[mt] = sw128(o);
    }
#pragma unroll
    for (int nb = 0; nb < 2; nb++) {
        const int n = wn * 32 + nb * 16 + ((l >> 4) << 3) + (l & 7);
        const uint32_t o = (uint32_t)(n * 128 + ((l >> 3) & 1) * 16);
        boff[nb] = 16384u + sw128(o);
    }

    // Prologue: chunks 0,1 into stages 0,1
#pragma unroll
    for (int p = 0; p < 2; p++) {
        load_chunk(p, tid, bm, bn, sb);
        CP_COMMIT();
    }

    for (int c = 0; c < NCHUNK; c++) {
        CP_WAIT1();                         // chunk c resident (c+1 may be in flight)
        __syncthreads();

        // buffer (c+2)%3 == (c-1)%3 was consumed at iter c-1; safe post-barrier
        if (c + 2 < NCHUNK) load_chunk(c + 2, tid, bm, bn, sb);
        CP_COMMIT();

        const uint32_t base = sb + (uint32_t)(c % NSTAGE) * STAGE_B;
#pragma unroll
        for (int k16 = 0; k16 < 4; k16++) {
            const uint32_t kx = (uint32_t)(k16 * 32);
            uint32_t a[4][4], b[2][4];
#pragma unroll
            for (int mt = 0; mt < 4; mt++)
                ldmatrix_x4(a[mt], base + (aoff[mt] ^ kx));
#pragma unroll
            for (int nb = 0; nb < 2; nb++)
                ldmatrix_x4(b[nb], base + (boff[nb] ^ kx));
#pragma unroll
            for (int mt = 0; mt < 4; mt++)
#pragma unroll
                for (int nt = 0; nt < 4; nt++)
                    mma_bf16(acc[mt][nt], a[mt], b[nt >> 1][(nt & 1) * 2],
                             b[nt >> 1][(nt & 1) * 2 + 1]);
        }
    }

    // Epilogue: fragment-direct float2 stores (4 lanes cover 32B contiguous)
    const int g = l >> 2;
    const int t4 = l & 3;
#pragma unroll
    for (int mt = 0; mt < 4; mt++) {
        const size_t r0 = (size_t)(bm + wm * 64 + mt * 16 + g);
#pragma unroll
        for (int nt = 0; nt < 4; nt++) {
            const int col = bn + wn * 32 + nt * 8 + t4 * 2;
            float2 v0 = make_float2(acc[mt][nt][0], acc[mt][nt][1]);
            float2 v1 = make_float2(acc[mt][nt][2], acc[mt][nt][3]);
            *reinterpret_cast<float2*>(g_ux + r0 * NN + col)       = v0;
            *reinterpret_cast<float2*>(g_ux + (r0 + 8) * NN + col) = v1;
        }
    }
}

// ---------------------------------------------------------------------------
// Scan: 8192 channels, one warp per 32 channels, cp.async smem pipeline
// ---------------------------------------------------------------------------
#define TSTG 16
#define SNSTG 4
#define NLOG2E (-1.4426950408889634f)

__device__ __forceinline__ float fast_ex2(float x) {
    float r;
    asm("ex2.approx.ftz.f32 %0, %1;" : "=f"(r) : "f"(x));
    return r;
}
__device__ __forceinline__ float fast_rcp(float x) {
    float r;
    asm("rcp.approx.ftz.f32 %0, %1;" : "=f"(r) : "f"(x));
    return r;
}

__global__ void __launch_bounds__(32) sru_scan_kernel(
    const float* __restrict__ x, const float* __restrict__ vf,
    const float* __restrict__ vr, const float* __restrict__ bf,
    const float* __restrict__ br, float* __restrict__ out) {
    __shared__ __align__(16) float s[SNSTG][TSTG][4][32];

    const int l = threadIdx.x;
    const int b = blockIdx.x >> 5;              // 32 blocks per batch
    const int h0 = (blockIdx.x & 31) * 32;
    const int h = h0 + l;

    const int strm = l >> 3;
    const int q = l & 7;

    const float* gsrc;
    size_t gstride;
    if (strm < 3) {
        gsrc = g_ux + (size_t)b * SS * NN + (size_t)strm * HH + h0 + q * 4;
        gstride = NN;
    } else {
        gsrc = x + (size_t)b * SS * HH + h0 + q * 4;
        gstride = HH;
    }
    const uint32_t sbase = s2u(&s[0][0][0][0]);

    const float vfn = NLOG2E * vf[h];
    const float vrn = NLOG2E * vr[h];
    const float bfh = bf[h];
    const float brh = br[h];
    float* yp = out + (size_t)b * SS * HH + h;

#define LOAD_STAGE(st, t0)                                                   \
    {                                                                        \
        const uint32_t d0 = sbase + (uint32_t)((st) & (SNSTG - 1)) * 8192 +  \
                            (uint32_t)(strm * 128 + q * 16);                 \
        _Pragma("unroll") for (int t = 0; t < TSTG; t++) {                   \
            CP_ASYNC16(d0 + (uint32_t)t * 512, gsrc + (size_t)((t0) + t) * gstride); \
        }                                                                    \
        CP_COMMIT();                                                         \
    }

    LOAD_STAGE(0, 0);
    LOAD_STAGE(1, TSTG);
    LOAD_STAGE(2, 2 * TSTG);

    float c = 0.0f;
    const int NST = SS / TSTG;  // 128
    for (int st = 0; st < NST; st++) {
        CP_WAIT2();
        __syncwarp();

        if (st + 3 < NST) {
            LOAD_STAGE(st + 3, (st + 3) * TSTG);
        } else {
            CP_COMMIT();
        }

        const float(*sp)[4][32] = s[st & (SNSTG - 1)];
        const int tb = st * TSTG;
#pragma unroll
        for (int t = 0; t < TSTG; t++) {
            const float xf = sp[t][0][l];
            const float xc = sp[t][1][l];
            const float xr = sp[t][2][l];
            const float xv = sp[t][3][l];
            const float ct = c;
            const float ef = fast_ex2(fmaf(vfn, ct, NLOG2E * (xf + bfh)));
            const float er = fast_ex2(fmaf(vrn, ct, NLOG2E * (xr + brh)));
            const float ft = fast_rcp(1.0f + ef);
            const float rt = fast_rcp(1.0f + er);
            c = fmaf(ft, ct - xc, xc);
            yp[(size_t)(tb + t) * HH] = fmaf(rt, c - xv, xv);
        }
        __syncwarp();
    }

    out[(size_t)BB * SS * HH + (size_t)b * HH + h] = c;
}

// ---------------------------------------------------------------------------
// Launch
// ---------------------------------------------------------------------------
extern "C" void kernel_launch(void* const* d_in, const int* in_sizes, int n_in,
                              void* d_out, int out_size) {
    const float* x  = (const float*)d_in[0];
    const float* W  = (const float*)d_in[1];
    const float* vf = (const float*)d_in[2];
    const float* vr = (const float*)d_in[3];
    const float* bf = (const float*)d_in[4];
    const float* br = (const float*)d_in[5];
    float* out = (float*)d_out;

    cvt_a_kernel<<<(MM * KK) / 1024, 256>>>(x);
    cvt_w_kernel<<<dim3(NN / 32, KK / 32), 256>>>(W);

    cudaFuncSetAttribute(sru_mma_gemm,
                         cudaFuncAttributeMaxDynamicSharedMemorySize, GEMM_SMEM);
    dim3 gg(NN / 128, MM / 128);  // (24, 128)
    sru_mma_gemm<<<gg, 256, GEMM_SMEM>>>();

    sru_scan_kernel<<<(BB * HH) / 32, 32>>>(x, vf, vr, bf, br, out);
}